// round 4
// baseline (speedup 1.0000x reference)
#include <cuda_runtime.h>
#include <cuda_bf16.h>
#include <climits>

// BallQuery via uniform spatial grid, 2 launches:
//   build_kernel  — single block: histogram + scan + scatter into cell-sorted array
//   query_kernel  — warp per query, 27-cell (9 contiguous row) scan, warp sort by index
// Outputs concatenated as float32:
//   [0,         N1*K)      mapping (indices, 0-padded)
//   [N1*K,      N1*K+N1)   counts  (min(#within, K))
//   [N1*K+N1,   +N1*K*3)   gathered neighbor xyz (0-padded)

#define NQ 8192
#define NP 8192
#define KNB 32
#define GRIDC 10
#define NCELL (GRIDC * GRIDC * GRIDC)
#define SCALEF 9.99f          // cell width 1/9.99 > radius -> +-1 cell coverage
#define CAP 128               // per-query hit buffer capacity
#define QWPB 16               // query warps per block
#define BT 1024               // build threads
#define PPT (NP / BT)         // points per build thread = 8

// Device scratch (no allocations allowed).
__device__ float4 g_sorted[NP];     // cell-sorted points: (x, y, z, |p|^2)
__device__ int    g_sidx[NP];       // original index of sorted point
__device__ int    g_start[NCELL + 1];

__device__ __forceinline__ int cell_of(float x) {
    int c = __float2int_rd(__fmul_rn(x, SCALEF));
    return min(max(c, 0), GRIDC - 1);
}

// Single-block build: zero + histogram + scan + scatter, all in shared memory.
__global__ void __launch_bounds__(BT, 1)
build_kernel(const float* __restrict__ p2)
{
    __shared__ int scnt[NCELL];   // histogram, then scatter cursors
    __shared__ int s[BT];         // scan workspace

    const int t = threadIdx.x;
    if (t < NCELL) scnt[t] = 0;
    __syncthreads();

    float px[PPT], py[PPT], pz[PPT];
    int   pc[PPT];
    #pragma unroll
    for (int r = 0; r < PPT; ++r) {
        const int i = t + BT * r;
        px[r] = p2[3 * i];
        py[r] = p2[3 * i + 1];
        pz[r] = p2[3 * i + 2];
        pc[r] = cell_of(px[r]) + GRIDC * cell_of(py[r])
              + GRIDC * GRIDC * cell_of(pz[r]);
        atomicAdd(&scnt[pc[r]], 1);
    }
    __syncthreads();

    // Hillis-Steele inclusive scan over 1024 slots (zeros beyond NCELL).
    int v = (t < NCELL) ? scnt[t] : 0;
    s[t] = v;
    __syncthreads();
    #pragma unroll
    for (int d = 1; d < BT; d <<= 1) {
        int add = (t >= d) ? s[t - d] : 0;
        __syncthreads();
        s[t] += add;
        __syncthreads();
    }
    if (t < NCELL) {
        g_start[t + 1] = s[t];
        scnt[t] = s[t] - v;       // exclusive prefix = scatter cursor
    }
    if (t == 0) g_start[0] = 0;
    __syncthreads();

    // Scatter: smem cursor atomics, direct global writes.
    #pragma unroll
    for (int r = 0; r < PPT; ++r) {
        const int i = t + BT * r;
        const int pos = atomicAdd(&scnt[pc[r]], 1);
        // |p|^2 with reference rounding: (x*x + y*y) + z*z, no FMA contraction.
        const float b = __fadd_rn(
            __fadd_rn(__fmul_rn(px[r], px[r]), __fmul_rn(py[r], py[r])),
            __fmul_rn(pz[r], pz[r]));
        g_sorted[pos] = make_float4(px[r], py[r], pz[r], b);
        g_sidx[pos] = i;
    }
}

// Warp bitonic ascending sort of 32*R ints, layout pos = lane + 32*r.
template <int R>
__device__ __forceinline__ void bitonic(int v[R], int lane) {
    const int n = 32 * R;
    #pragma unroll
    for (int k = 2; k <= n; k <<= 1) {
        #pragma unroll
        for (int j = k >> 1; j > 0; j >>= 1) {
            if (j >= 32) {
                const int jr = j >> 5;
                #pragma unroll
                for (int r = 0; r < R; ++r) {
                    const int pr = r ^ jr;
                    if (pr > r) {
                        const bool up = (((lane + 32 * r) & k) == 0);
                        int a = v[r], b = v[pr];
                        if ((a > b) == up) { v[r] = b; v[pr] = a; }
                    }
                }
            } else {
                #pragma unroll
                for (int r = 0; r < R; ++r) {
                    int part = __shfl_xor_sync(0xffffffffu, v[r], j);
                    const bool up = (((lane + 32 * r) & k) == 0);
                    const bool lowr = ((lane & j) == 0);
                    v[r] = (lowr == up) ? min(v[r], part) : max(v[r], part);
                }
            }
        }
    }
}

__global__ void __launch_bounds__(QWPB * 32)
query_kernel(const float* __restrict__ p1, float* __restrict__ out)
{
    __shared__ float4 hitbuf[QWPB][CAP];

    const int warp = threadIdx.x >> 5;
    const int lane = threadIdx.x & 31;
    const int q = blockIdx.x * QWPB + warp;

    const float qx = p1[3 * q], qy = p1[3 * q + 1], qz = p1[3 * q + 2];
    const float a = __fadd_rn(__fadd_rn(__fmul_rn(qx, qx), __fmul_rn(qy, qy)),
                              __fmul_rn(qz, qz));
    const float R2 = (float)(0.1 * 0.1);

    const int cx = cell_of(qx), cy = cell_of(qy), cz = cell_of(qz);
    const int xlo = max(cx - 1, 0), xhi = min(cx + 1, GRIDC - 1);
    const int ylo = max(cy - 1, 0), yhi = min(cy + 1, GRIDC - 1);
    const int zlo = max(cz - 1, 0), zhi = min(cz + 1, GRIDC - 1);

    const unsigned below = (1u << lane) - 1u;
    int cnt = 0;

    for (int ez = zlo; ez <= zhi; ++ez) {
        for (int ey = ylo; ey <= yhi; ++ey) {
            const int base = GRIDC * ey + GRIDC * GRIDC * ez;
            const int s = g_start[xlo + base];
            const int e = g_start[xhi + base + 1];  // x-contiguous row of 3 cells
            for (int t0 = s; t0 < e; t0 += 32) {
                const int t = t0 + lane;
                const bool act = (t < e);
                float4 p = make_float4(0.f, 0.f, 0.f, 4e30f);
                if (act) p = __ldg(&g_sorted[t]);
                // Gram-trick distance, reference rounding.
                const float c = __fadd_rn(
                    __fadd_rn(__fmul_rn(qx, p.x), __fmul_rn(qy, p.y)),
                    __fmul_rn(qz, p.z));
                const float d2 = __fsub_rn(__fadd_rn(a, p.w),
                                           __fmul_rn(2.0f, c));
                const bool hit = act && (d2 <= R2);
                const unsigned m = __ballot_sync(0xffffffffu, hit);
                if (m) {
                    if (hit) {
                        const int slot = cnt + __popc(m & below);
                        if (slot < CAP) {
                            const int idx = __ldg(&g_sidx[t]);
                            hitbuf[warp][slot] =
                                make_float4(p.x, p.y, p.z, __int_as_float(idx));
                        }
                    }
                    cnt += __popc(m);
                }
            }
        }
    }

    const int cc = min(cnt, KNB);
    const int nb = min(cnt, CAP);

    // Sort hit keys (idx<<7 | slot) ascending; idx unique -> deterministic.
    int key0;
    if (cnt <= 64) {
        int v[2];
        #pragma unroll
        for (int r = 0; r < 2; ++r) {
            const int slot = lane + 32 * r;
            v[r] = (slot < nb)
                ? ((__float_as_int(hitbuf[warp][slot].w) << 7) | slot)
                : INT_MAX;
        }
        bitonic<2>(v, lane);
        key0 = v[0];
    } else {
        int v[4];
        #pragma unroll
        for (int r = 0; r < 4; ++r) {
            const int slot = lane + 32 * r;
            v[r] = (slot < nb)
                ? ((__float_as_int(hitbuf[warp][slot].w) << 7) | slot)
                : INT_MAX;
        }
        bitonic<4>(v, lane);
        key0 = v[0];
    }

    float* __restrict__ mapq = out + (size_t)q * KNB;
    float* __restrict__ cntf = out + (size_t)NQ * KNB;
    float* __restrict__ outq = out + (size_t)NQ * KNB + NQ + (size_t)q * KNB * 3;

    if (lane < cc) {
        const int idx = key0 >> 7;
        const int slot = key0 & (CAP - 1);
        const float4 h = hitbuf[warp][slot];
        mapq[lane] = (float)idx;
        outq[3 * lane + 0] = h.x;
        outq[3 * lane + 1] = h.y;
        outq[3 * lane + 2] = h.z;
    } else {
        mapq[lane] = 0.0f;
        outq[3 * lane + 0] = 0.0f;
        outq[3 * lane + 1] = 0.0f;
        outq[3 * lane + 2] = 0.0f;
    }
    if (lane == 0) cntf[q] = (float)cc;
}

extern "C" void kernel_launch(void* const* d_in, const int* in_sizes, int n_in,
                              void* d_out, int out_size)
{
    (void)in_sizes; (void)n_in; (void)out_size;
    const float* p1 = (const float*)d_in[0];
    const float* p2 = (const float*)d_in[1];
    float* out = (float*)d_out;

    build_kernel<<<1, BT>>>(p2);
    query_kernel<<<NQ / QWPB, QWPB * 32>>>(p1, out);
}

// round 5
// speedup vs baseline: 1.1794x; 1.1794x over previous
#include <cuda_runtime.h>
#include <cuda_bf16.h>
#include <climits>

// BallQuery via uniform spatial grid, 2 launches:
//   build_kernel — persistent 64-block kernel (histogram / scan / scatter with
//                  software grid barriers)
//   query_kernel — warp per query, 27-cell (9 contiguous row) scan, warp sort
// Outputs concatenated as float32:
//   [0,         N1*K)      mapping (indices, 0-padded)
//   [N1*K,      N1*K+N1)   counts  (min(#within, K))
//   [N1*K+N1,   +N1*K*3)   gathered neighbor xyz (0-padded)

#define NQ 8192
#define NP 8192
#define KNB 32
#define GRIDC 10
#define NCELL (GRIDC * GRIDC * GRIDC)
#define SCALEF 9.99f          // cell width 1/9.99 > radius -> +-1 cell coverage
#define CAP 128               // per-query hit buffer capacity
#define QWPB 16               // query warps per block
#define BBLK 64               // build blocks
#define BTHR 128              // build threads per block (BBLK*BTHR == NP)

// Device scratch (no allocations allowed).
__device__ float4 g_sorted[NP];       // cell-sorted points: (x, y, z, |p|^2)
__device__ int    g_sidx[NP];         // original index of sorted point
__device__ int    g_count[NCELL];     // zero at start of every run (see scan)
__device__ int    g_start[NCELL + 1];
__device__ int    g_offset[NCELL];
__device__ volatile unsigned g_barcnt = 0;
__device__ volatile unsigned g_bargen = 0;

__device__ __forceinline__ int cell_of(float x) {
    int c = __float2int_rd(__fmul_rn(x, SCALEF));
    return min(max(c, 0), GRIDC - 1);
}

// Software grid barrier (all BBLK blocks are co-resident: 64 blocks x 128 thr).
__device__ __forceinline__ void grid_barrier() {
    __syncthreads();
    if (threadIdx.x == 0) {
        unsigned gen = g_bargen;
        __threadfence();
        if (atomicAdd((unsigned*)&g_barcnt, 1u) == BBLK - 1) {
            g_barcnt = 0;
            __threadfence();
            g_bargen = gen + 1;
        } else {
            while (g_bargen == gen) { }
            __threadfence();
        }
    }
    __syncthreads();
}

__global__ void __launch_bounds__(BTHR, 1)
build_kernel(const float* __restrict__ p2)
{
    const int i = blockIdx.x * BTHR + threadIdx.x;   // one point per thread

    const float x = p2[3 * i];
    const float y = p2[3 * i + 1];
    const float z = p2[3 * i + 2];
    const int c = cell_of(x) + GRIDC * cell_of(y) + GRIDC * GRIDC * cell_of(z);

    atomicAdd(&g_count[c], 1);
    grid_barrier();

    // Block 0: exclusive scan of g_count -> g_start / g_offset; re-zero g_count.
    if (blockIdx.x == 0) {
        __shared__ int bsum[BTHR];
        const int t = threadIdx.x;
        int loc[8];
        int tot = 0;
        #pragma unroll
        for (int k = 0; k < 8; ++k) {
            const int j = t * 8 + k;
            const int v = (j < NCELL) ? g_count[j] : 0;
            loc[k] = v;
            tot += v;
        }
        bsum[t] = tot;
        __syncthreads();
        #pragma unroll
        for (int d = 1; d < BTHR; d <<= 1) {
            int add = (t >= d) ? bsum[t - d] : 0;
            __syncthreads();
            bsum[t] += add;
            __syncthreads();
        }
        int run = bsum[t] - tot;     // exclusive block offset
        #pragma unroll
        for (int k = 0; k < 8; ++k) {
            const int j = t * 8 + k;
            if (j < NCELL) {
                g_start[j] = run;
                g_offset[j] = run;
                run += loc[k];
                g_count[j] = 0;      // clean for the next run/replay
                if (j == NCELL - 1) g_start[NCELL] = run;
            }
        }
    }
    grid_barrier();

    // Scatter (order within a cell is nondeterministic; the query-side sort by
    // original index makes the final output deterministic).
    const int pos = atomicAdd(&g_offset[c], 1);
    // |p|^2 with reference rounding: (x*x + y*y) + z*z, no FMA contraction.
    const float b = __fadd_rn(__fadd_rn(__fmul_rn(x, x), __fmul_rn(y, y)),
                              __fmul_rn(z, z));
    g_sorted[pos] = make_float4(x, y, z, b);
    g_sidx[pos] = i;
}

// Warp bitonic ascending sort of 32*R ints, layout pos = lane + 32*r.
template <int R>
__device__ __forceinline__ void bitonic(int v[R], int lane) {
    const int n = 32 * R;
    #pragma unroll
    for (int k = 2; k <= n; k <<= 1) {
        #pragma unroll
        for (int j = k >> 1; j > 0; j >>= 1) {
            if (j >= 32) {
                const int jr = j >> 5;
                #pragma unroll
                for (int r = 0; r < R; ++r) {
                    const int pr = r ^ jr;
                    if (pr > r) {
                        const bool up = (((lane + 32 * r) & k) == 0);
                        int a = v[r], b = v[pr];
                        if ((a > b) == up) { v[r] = b; v[pr] = a; }
                    }
                }
            } else {
                #pragma unroll
                for (int r = 0; r < R; ++r) {
                    int part = __shfl_xor_sync(0xffffffffu, v[r], j);
                    const bool up = (((lane + 32 * r) & k) == 0);
                    const bool lowr = ((lane & j) == 0);
                    v[r] = (lowr == up) ? min(v[r], part) : max(v[r], part);
                }
            }
        }
    }
}

__global__ void __launch_bounds__(QWPB * 32)
query_kernel(const float* __restrict__ p1, float* __restrict__ out)
{
    __shared__ int keybuf[QWPB][CAP];     // packed (idx<<13)|sorted_pos
    __shared__ int sstart[NCELL + 1];     // block-local copy of g_start

    const int tid = threadIdx.x;
    for (int i = tid; i < NCELL + 1; i += QWPB * 32) sstart[i] = g_start[i];
    __syncthreads();

    const int warp = tid >> 5;
    const int lane = tid & 31;
    const int q = blockIdx.x * QWPB + warp;

    const float qx = p1[3 * q], qy = p1[3 * q + 1], qz = p1[3 * q + 2];
    const float a = __fadd_rn(__fadd_rn(__fmul_rn(qx, qx), __fmul_rn(qy, qy)),
                              __fmul_rn(qz, qz));
    const float R2 = (float)(0.1 * 0.1);

    const int cx = cell_of(qx), cy = cell_of(qy), cz = cell_of(qz);
    const int xlo = max(cx - 1, 0), xhi = min(cx + 1, GRIDC - 1);
    const int ylo = max(cy - 1, 0), yhi = min(cy + 1, GRIDC - 1);
    const int zlo = max(cz - 1, 0), zhi = min(cz + 1, GRIDC - 1);

    const unsigned below = (1u << lane) - 1u;
    int cnt = 0;

    for (int ez = zlo; ez <= zhi; ++ez) {
        for (int ey = ylo; ey <= yhi; ++ey) {
            const int base = GRIDC * ey + GRIDC * GRIDC * ez;
            const int s = sstart[xlo + base];
            const int e = sstart[xhi + base + 1];  // x-contiguous row of 3 cells
            for (int t0 = s; t0 < e; t0 += 32) {
                const int t = t0 + lane;
                const bool act = (t < e);
                float4 p = make_float4(0.f, 0.f, 0.f, 4e30f);
                if (act) p = __ldg(&g_sorted[t]);
                // Gram-trick distance, reference rounding.
                const float c = __fadd_rn(
                    __fadd_rn(__fmul_rn(qx, p.x), __fmul_rn(qy, p.y)),
                    __fmul_rn(qz, p.z));
                const float d2 = __fsub_rn(__fadd_rn(a, p.w),
                                           __fmul_rn(2.0f, c));
                const bool hit = act && (d2 <= R2);
                const unsigned m = __ballot_sync(0xffffffffu, hit);
                if (m) {
                    if (hit) {
                        const int slot = cnt + __popc(m & below);
                        if (slot < CAP) {
                            const int idx = __ldg(&g_sidx[t]);
                            keybuf[warp][slot] = (idx << 13) | t;
                        }
                    }
                    cnt += __popc(m);
                }
            }
        }
    }

    const int cc = min(cnt, KNB);
    const int nb = min(cnt, CAP);

    // Sort keys ascending; idx unique -> deterministic order by original index.
    int key0;
    if (cnt <= 64) {
        int v[2];
        #pragma unroll
        for (int r = 0; r < 2; ++r) {
            const int slot = lane + 32 * r;
            v[r] = (slot < nb) ? keybuf[warp][slot] : INT_MAX;
        }
        bitonic<2>(v, lane);
        key0 = v[0];
    } else {
        int v[4];
        #pragma unroll
        for (int r = 0; r < 4; ++r) {
            const int slot = lane + 32 * r;
            v[r] = (slot < nb) ? keybuf[warp][slot] : INT_MAX;
        }
        bitonic<4>(v, lane);
        key0 = v[0];
    }

    float* __restrict__ mapq = out + (size_t)q * KNB;
    float* __restrict__ cntf = out + (size_t)NQ * KNB;
    float* __restrict__ outq = out + (size_t)NQ * KNB + NQ + (size_t)q * KNB * 3;

    if (lane < cc) {
        const int t = key0 & (NP - 1);
        const float4 h = __ldg(&g_sorted[t]);
        mapq[lane] = (float)(key0 >> 13);
        outq[3 * lane + 0] = h.x;
        outq[3 * lane + 1] = h.y;
        outq[3 * lane + 2] = h.z;
    } else {
        mapq[lane] = 0.0f;
        outq[3 * lane + 0] = 0.0f;
        outq[3 * lane + 1] = 0.0f;
        outq[3 * lane + 2] = 0.0f;
    }
    if (lane == 0) cntf[q] = (float)cc;
}

extern "C" void kernel_launch(void* const* d_in, const int* in_sizes, int n_in,
                              void* d_out, int out_size)
{
    (void)in_sizes; (void)n_in; (void)out_size;
    const float* p1 = (const float*)d_in[0];
    const float* p2 = (const float*)d_in[1];
    float* out = (float*)d_out;

    build_kernel<<<BBLK, BTHR>>>(p2);
    query_kernel<<<NQ / QWPB, QWPB * 32>>>(p1, out);
}